// round 3
// baseline (speedup 1.0000x reference)
#include <cuda_runtime.h>
#include <cuda_bf16.h>

// Upsample2d (up=2, binomial 4-tap) == separable interp:
//   out[2m]   = 0.25*x[m-1] + 0.75*x[m]
//   out[2m+1] = 0.75*x[m]   + 0.25*x[m+1]
// R3: one warp spans a full input row (32 lanes x float4). Halo = intra-warp
// shfl only (row ends are image edges -> 0). Rolling vertical state, CHUNK=4
// batched float4 loads, streaming float4 stores.

#define W_IN  128
#define H_IN  128
#define W_OUT 256
#define H_OUT 256
#define WARPS 8      // warps per block
#define RPW   8      // input rows per warp strip
#define CHUNK 4      // rows batched per load wave
// block covers WARPS*RPW = 64 input rows -> 2 blocks per image

__device__ __forceinline__ void compute_h(float4 a, int lane, float* __restrict__ h) {
    float left  = __shfl_up_sync(0xffffffffu, a.w, 1);
    float right = __shfl_down_sync(0xffffffffu, a.x, 1);
    if (lane == 0)  left  = 0.0f;
    if (lane == 31) right = 0.0f;
    h[0] = 0.25f * left + 0.75f * a.x;
    h[1] = 0.75f * a.x  + 0.25f * a.y;
    h[2] = 0.25f * a.x  + 0.75f * a.y;
    h[3] = 0.75f * a.y  + 0.25f * a.z;
    h[4] = 0.25f * a.y  + 0.75f * a.z;
    h[5] = 0.75f * a.z  + 0.25f * a.w;
    h[6] = 0.25f * a.z  + 0.75f * a.w;
    h[7] = 0.75f * a.w  + 0.25f * right;
}

__device__ __forceinline__ void store8_cs(float* p, const float* __restrict__ w0,
                                          const float* __restrict__ w1,
                                          float c0, float c1) {
    float4 lo = make_float4(c0 * w0[0] + c1 * w1[0], c0 * w0[1] + c1 * w1[1],
                            c0 * w0[2] + c1 * w1[2], c0 * w0[3] + c1 * w1[3]);
    float4 hi = make_float4(c0 * w0[4] + c1 * w1[4], c0 * w0[5] + c1 * w1[5],
                            c0 * w0[6] + c1 * w1[6], c0 * w0[7] + c1 * w1[7]);
    __stcs(reinterpret_cast<float4*>(p),     lo);
    __stcs(reinterpret_cast<float4*>(p + 4), hi);
}

__global__ __launch_bounds__(WARPS * 32)
void Upsample_63797444215162_kernel(const float* __restrict__ x,
                                    float* __restrict__ out) {
    const int tid  = threadIdx.x;
    const int warp = tid >> 5;
    const int lane = tid & 31;
    const int img  = blockIdx.x >> 1;           // 2 blocks per image
    const int half = blockIdx.x & 1;

    const float* __restrict__ xi = x   + (size_t)img * (H_IN * W_IN);
    float*       __restrict__ oi = out + (size_t)img * (H_OUT * W_OUT);

    const int r0 = half * (WARPS * RPW) + warp * RPW;   // strip start row
    const int c0 = lane * 4;                            // input col base
    const int oc = lane * 8;                            // output col base

    float hp[8];                                        // h(n-1), rolled
    if (r0 == 0) {
        #pragma unroll
        for (int j = 0; j < 8; ++j) hp[j] = 0.0f;
    } else {
        float4 a = *reinterpret_cast<const float4*>(xi + (r0 - 1) * W_IN + c0);
        compute_h(a, lane, hp);
    }

    #pragma unroll
    for (int base = r0; base < r0 + RPW; base += CHUNK) {
        float4 v[CHUNK];
        #pragma unroll
        for (int k = 0; k < CHUNK; ++k)
            v[k] = *reinterpret_cast<const float4*>(xi + (base + k) * W_IN + c0);

        #pragma unroll
        for (int k = 0; k < CHUNK; ++k) {
            const int n = base + k;
            float h[8];
            compute_h(v[k], lane, h);

            // out row 2n-1 = 0.75*h(n-1) + 0.25*h(n)   (row -1 doesn't exist)
            if (n > 0)
                store8_cs(oi + (2 * n - 1) * W_OUT + oc, hp, h, 0.75f, 0.25f);
            // out row 2n   = 0.25*h(n-1) + 0.75*h(n)
            store8_cs(oi + (2 * n) * W_OUT + oc, hp, h, 0.25f, 0.75f);

            #pragma unroll
            for (int j = 0; j < 8; ++j) hp[j] = h[j];
        }
    }

    // last output row 2H-1 = 0.75*h(H-1), owned by the last strip
    if (r0 + RPW == H_IN) {
        float4 lo = make_float4(0.75f * hp[0], 0.75f * hp[1], 0.75f * hp[2], 0.75f * hp[3]);
        float4 hi = make_float4(0.75f * hp[4], 0.75f * hp[5], 0.75f * hp[6], 0.75f * hp[7]);
        float* p = oi + (H_OUT - 1) * W_OUT + oc;
        __stcs(reinterpret_cast<float4*>(p),     lo);
        __stcs(reinterpret_cast<float4*>(p + 4), hi);
    }
}

extern "C" void kernel_launch(void* const* d_in, const int* in_sizes, int n_in,
                              void* d_out, int out_size) {
    const float* x = (const float*)d_in[0];   // [8,128,128,128] fp32
    // d_in[1] is the fixed 4x4 binomial kernel; weights folded into code.
    float* out = (float*)d_out;               // [8,128,256,256] fp32

    const int n_img = in_sizes[0] / (H_IN * W_IN);   // B*C = 1024
    dim3 block(WARPS * 32);
    dim3 grid(n_img * 2);                            // 2 blocks per image
    Upsample_63797444215162_kernel<<<grid, block>>>(x, out);
}

// round 4
// speedup vs baseline: 1.1149x; 1.1149x over previous
#include <cuda_runtime.h>
#include <cuda_bf16.h>

// Upsample2d (up=2, binomial 4-tap) == separable interp:
//   out[2m]   = 0.25*x[m-1] + 0.75*x[m]
//   out[2m+1] = 0.75*x[m]   + 0.25*x[m+1]
// R4: warp spans HALF an input row (32 lanes x float2) so each lane emits ONE
// contiguous float4 per output row (coalesced 512B warp stores). Halo: shfl +
// one predicated seam scalar per row. CHUNK=4 batched loads, reg-capped.

#define W_IN  128
#define H_IN  128
#define W_OUT 256
#define H_OUT 256
#define RPT   32     // input rows per warp strip (4 strips x 32 = 128)
#define CHUNK 4

__global__ __launch_bounds__(256, 5)
void Upsample_63797444215162_kernel(const float* __restrict__ x,
                                    float* __restrict__ out) {
    const int tid  = threadIdx.x;
    const int warp = tid >> 5;
    const int lane = tid & 31;
    const int half  = warp & 1;          // 0: cols [0,64), 1: cols [64,128)
    const int strip = warp >> 1;         // 0..3
    const int img  = blockIdx.x;

    const float* __restrict__ xi = x   + (size_t)img * (H_IN * W_IN);
    float*       __restrict__ oi = out + (size_t)img * (H_OUT * W_OUT);

    const int r0 = strip * RPT;
    const int c0 = half * 64 + lane * 2;     // input col base (float2)
    const int oc = 2 * c0;                   // output col base (float4)
    const int cs = 64 - half;                // seam col: 64 (half0) or 63 (half1)
    const bool seam = (half == 0) ? (lane == 31) : (lane == 0);

    float hE0p, hO0p, hE1p, hO1p;            // h(n-1), rolled

    if (r0 == 0) {
        hE0p = hO0p = hE1p = hO1p = 0.0f;
    } else {
        const float* row = xi + (r0 - 1) * W_IN;
        float2 bc = *reinterpret_cast<const float2*>(row + c0);
        float  s  = seam ? __ldg(row + cs) : 0.0f;
        float a = __shfl_up_sync(0xffffffffu, bc.y, 1);
        float d = __shfl_down_sync(0xffffffffu, bc.x, 1);
        if (lane == 0)  a = (half == 1) ? s : 0.0f;
        if (lane == 31) d = (half == 0) ? s : 0.0f;
        hE0p = 0.25f * a    + 0.75f * bc.x;
        hO0p = 0.75f * bc.x + 0.25f * bc.y;
        hE1p = 0.25f * bc.x + 0.75f * bc.y;
        hO1p = 0.75f * bc.y + 0.25f * d;
    }

    for (int base = r0; base < r0 + RPT; base += CHUNK) {
        float2 v[CHUNK];
        float  s[CHUNK];
        #pragma unroll
        for (int k = 0; k < CHUNK; ++k) {
            const float* row = xi + (base + k) * W_IN;
            v[k] = *reinterpret_cast<const float2*>(row + c0);
            if (seam) s[k] = __ldg(row + cs);
        }

        #pragma unroll
        for (int k = 0; k < CHUNK; ++k) {
            const int n = base + k;
            float2 bc = v[k];
            float a = __shfl_up_sync(0xffffffffu, bc.y, 1);
            float d = __shfl_down_sync(0xffffffffu, bc.x, 1);
            if (lane == 0)  a = (half == 1) ? s[k] : 0.0f;
            if (lane == 31) d = (half == 0) ? s[k] : 0.0f;

            float hE0 = 0.25f * a    + 0.75f * bc.x;
            float hO0 = 0.75f * bc.x + 0.25f * bc.y;
            float hE1 = 0.25f * bc.x + 0.75f * bc.y;
            float hO1 = 0.75f * bc.y + 0.25f * d;

            // out row 2n-1 = 0.75*h(n-1) + 0.25*h(n)
            if (n > 0) {
                float4 o = make_float4(0.75f * hE0p + 0.25f * hE0,
                                       0.75f * hO0p + 0.25f * hO0,
                                       0.75f * hE1p + 0.25f * hE1,
                                       0.75f * hO1p + 0.25f * hO1);
                __stcs(reinterpret_cast<float4*>(oi + (2 * n - 1) * W_OUT + oc), o);
            }
            // out row 2n = 0.25*h(n-1) + 0.75*h(n)
            {
                float4 o = make_float4(0.25f * hE0p + 0.75f * hE0,
                                       0.25f * hO0p + 0.75f * hO0,
                                       0.25f * hE1p + 0.75f * hE1,
                                       0.25f * hO1p + 0.75f * hO1);
                __stcs(reinterpret_cast<float4*>(oi + (2 * n) * W_OUT + oc), o);
            }

            hE0p = hE0; hO0p = hO0; hE1p = hE1; hO1p = hO1;
        }
    }

    // last output row 2H-1 = 0.75*h(H-1), owned by the last strip
    if (r0 + RPT == H_IN) {
        float4 o = make_float4(0.75f * hE0p, 0.75f * hO0p,
                               0.75f * hE1p, 0.75f * hO1p);
        __stcs(reinterpret_cast<float4*>(oi + (H_OUT - 1) * W_OUT + oc), o);
    }
}

extern "C" void kernel_launch(void* const* d_in, const int* in_sizes, int n_in,
                              void* d_out, int out_size) {
    const float* x = (const float*)d_in[0];   // [8,128,128,128] fp32
    // d_in[1] is the fixed 4x4 binomial kernel; weights folded into code.
    float* out = (float*)d_out;               // [8,128,256,256] fp32

    const int n_img = in_sizes[0] / (H_IN * W_IN);   // B*C = 1024
    Upsample_63797444215162_kernel<<<n_img, 256>>>(x, out);
}

// round 5
// speedup vs baseline: 1.1632x; 1.0434x over previous
#include <cuda_runtime.h>
#include <cuda_bf16.h>

// Upsample2d (up=2, binomial 4-tap) == separable interp:
//   out[2m]   = 0.25*x[m-1] + 0.75*x[m]
//   out[2m+1] = 0.75*x[m]   + 0.25*x[m+1]
// R5: persistent fully-resident grid (444 blocks = 3/SM x 148), warp-strided
// fine work units (img, half, 16-row strip) to kill wave-tail quantization.
// CHUNK=8 batched loads (MLP=8), coalesced float4 streaming stores, shfl halo
// + one predicated seam scalar per row.

#define W_IN  128
#define H_IN  128
#define W_OUT 256
#define H_OUT 256
#define ROWS_PER_UNIT 16
#define CHUNK 8
#define NBLOCKS 444                    // 3 per SM x 148 SMs
#define NWARPS  (NBLOCKS * 8)          // 3552
#define NUNITS  (1024 * 2 * 8)         // img x half x strip16 = 16384

__global__ __launch_bounds__(256, 3)
void Upsample_63797444215162_kernel(const float* __restrict__ x,
                                    float* __restrict__ out) {
    const int tid  = threadIdx.x;
    const int warp = tid >> 5;
    const int lane = tid & 31;
    const int g    = blockIdx.x * 8 + warp;    // global warp id

    for (int t = g; t < NUNITS; t += NWARPS) {
        const int img   = t >> 4;              // 16 units per image
        const int rem   = t & 15;
        const int half  = rem & 1;             // 0: cols [0,64), 1: [64,128)
        const int strip = rem >> 1;            // 0..7
        const int r0    = strip * ROWS_PER_UNIT;

        const float* __restrict__ xi = x   + (size_t)img * (H_IN * W_IN);
        float*       __restrict__ oi = out + (size_t)img * (H_OUT * W_OUT);

        const int c0 = half * 64 + lane * 2;   // input col base (float2)
        const int oc = 2 * c0;                 // output col base (float4)
        const int cs = 64 - half;              // seam col: 64 (half0) / 63 (half1)
        const bool seam = (half == 0) ? (lane == 31) : (lane == 0);

        float hE0p, hO0p, hE1p, hO1p;          // h(n-1), rolled

        if (r0 == 0) {
            hE0p = hO0p = hE1p = hO1p = 0.0f;
        } else {
            const float* row = xi + (r0 - 1) * W_IN;
            float2 bc = *reinterpret_cast<const float2*>(row + c0);
            float  sv = seam ? __ldg(row + cs) : 0.0f;
            float a = __shfl_up_sync(0xffffffffu, bc.y, 1);
            float d = __shfl_down_sync(0xffffffffu, bc.x, 1);
            if (lane == 0)  a = (half == 1) ? sv : 0.0f;
            if (lane == 31) d = (half == 0) ? sv : 0.0f;
            hE0p = 0.25f * a    + 0.75f * bc.x;
            hO0p = 0.75f * bc.x + 0.25f * bc.y;
            hE1p = 0.25f * bc.x + 0.75f * bc.y;
            hO1p = 0.75f * bc.y + 0.25f * d;
        }

        #pragma unroll
        for (int cb = 0; cb < ROWS_PER_UNIT / CHUNK; ++cb) {
            const int base = r0 + cb * CHUNK;
            float2 v[CHUNK];
            float  s[CHUNK];
            #pragma unroll
            for (int k = 0; k < CHUNK; ++k) {
                const float* row = xi + (base + k) * W_IN;
                v[k] = *reinterpret_cast<const float2*>(row + c0);
                if (seam) s[k] = __ldg(row + cs);
            }

            #pragma unroll
            for (int k = 0; k < CHUNK; ++k) {
                const int n = base + k;
                float2 bc = v[k];
                float a = __shfl_up_sync(0xffffffffu, bc.y, 1);
                float d = __shfl_down_sync(0xffffffffu, bc.x, 1);
                if (lane == 0)  a = (half == 1) ? s[k] : 0.0f;
                if (lane == 31) d = (half == 0) ? s[k] : 0.0f;

                float hE0 = 0.25f * a    + 0.75f * bc.x;
                float hO0 = 0.75f * bc.x + 0.25f * bc.y;
                float hE1 = 0.25f * bc.x + 0.75f * bc.y;
                float hO1 = 0.75f * bc.y + 0.25f * d;

                // out row 2n-1 = 0.75*h(n-1) + 0.25*h(n)
                if (n > 0) {
                    float4 o = make_float4(0.75f * hE0p + 0.25f * hE0,
                                           0.75f * hO0p + 0.25f * hO0,
                                           0.75f * hE1p + 0.25f * hE1,
                                           0.75f * hO1p + 0.25f * hO1);
                    __stcs(reinterpret_cast<float4*>(oi + (2 * n - 1) * W_OUT + oc), o);
                }
                // out row 2n = 0.25*h(n-1) + 0.75*h(n)
                {
                    float4 o = make_float4(0.25f * hE0p + 0.75f * hE0,
                                           0.25f * hO0p + 0.75f * hO0,
                                           0.25f * hE1p + 0.75f * hE1,
                                           0.25f * hO1p + 0.75f * hO1);
                    __stcs(reinterpret_cast<float4*>(oi + (2 * n) * W_OUT + oc), o);
                }

                hE0p = hE0; hO0p = hO0; hE1p = hE1; hO1p = hO1;
            }
        }

        // last output row 2H-1 = 0.75*h(H-1), owned by the last strip
        if (r0 + ROWS_PER_UNIT == H_IN) {
            float4 o = make_float4(0.75f * hE0p, 0.75f * hO0p,
                                   0.75f * hE1p, 0.75f * hO1p);
            __stcs(reinterpret_cast<float4*>(oi + (H_OUT - 1) * W_OUT + oc), o);
        }
    }
}

extern "C" void kernel_launch(void* const* d_in, const int* in_sizes, int n_in,
                              void* d_out, int out_size) {
    const float* x = (const float*)d_in[0];   // [8,128,128,128] fp32
    // d_in[1] is the fixed 4x4 binomial kernel; weights folded into code.
    float* out = (float*)d_out;               // [8,128,256,256] fp32

    Upsample_63797444215162_kernel<<<NBLOCKS, 256>>>(x, out);
}

// round 6
// speedup vs baseline: 1.2546x; 1.0786x over previous
#include <cuda_runtime.h>
#include <cuda_bf16.h>

// Upsample2d (up=2, binomial 4-tap) == separable interp:
//   out[2m]   = 0.25*x[m-1] + 0.75*x[m]
//   out[2m+1] = 0.75*x[m]   + 0.25*x[m+1]
// R6: warp spans a FULL input row (32 lanes x float4), halo purely intra-warp
// (row ends = image edges). Each lane emits its 8 output floats with a single
// 256-bit store (st.global.cs.v8.f32, sm_100+) -> one contiguous 1024B warp
// store per output row. CHUNK=4 batched float4 loads.

#define W_IN  128
#define H_IN  128
#define W_OUT 256
#define H_OUT 256
#define WARPS 8
#define RPW   8      // input rows per warp strip
#define CHUNK 4

__device__ __forceinline__ void compute_h(float4 a, int lane, float* __restrict__ h) {
    float left  = __shfl_up_sync(0xffffffffu, a.w, 1);
    float right = __shfl_down_sync(0xffffffffu, a.x, 1);
    if (lane == 0)  left  = 0.0f;
    if (lane == 31) right = 0.0f;
    h[0] = 0.25f * left + 0.75f * a.x;
    h[1] = 0.75f * a.x  + 0.25f * a.y;
    h[2] = 0.25f * a.x  + 0.75f * a.y;
    h[3] = 0.75f * a.y  + 0.25f * a.z;
    h[4] = 0.25f * a.y  + 0.75f * a.z;
    h[5] = 0.75f * a.z  + 0.25f * a.w;
    h[6] = 0.25f * a.z  + 0.75f * a.w;
    h[7] = 0.75f * a.w  + 0.25f * right;
}

__device__ __forceinline__ void store_row_v8(float* p,
                                             const float* __restrict__ w0,
                                             const float* __restrict__ w1,
                                             float c0, float c1) {
    float o0 = c0 * w0[0] + c1 * w1[0];
    float o1 = c0 * w0[1] + c1 * w1[1];
    float o2 = c0 * w0[2] + c1 * w1[2];
    float o3 = c0 * w0[3] + c1 * w1[3];
    float o4 = c0 * w0[4] + c1 * w1[4];
    float o5 = c0 * w0[5] + c1 * w1[5];
    float o6 = c0 * w0[6] + c1 * w1[6];
    float o7 = c0 * w0[7] + c1 * w1[7];
    asm volatile("st.global.cs.v8.f32 [%0], {%1,%2,%3,%4,%5,%6,%7,%8};"
                 :: "l"(p), "f"(o0), "f"(o1), "f"(o2), "f"(o3),
                    "f"(o4), "f"(o5), "f"(o6), "f"(o7)
                 : "memory");
}

__global__ __launch_bounds__(WARPS * 32)
void Upsample_63797444215162_kernel(const float* __restrict__ x,
                                    float* __restrict__ out) {
    const int tid  = threadIdx.x;
    const int warp = tid >> 5;
    const int lane = tid & 31;
    const int img  = blockIdx.x >> 1;           // 2 blocks per image
    const int half = blockIdx.x & 1;

    const float* __restrict__ xi = x   + (size_t)img * (H_IN * W_IN);
    float*       __restrict__ oi = out + (size_t)img * (H_OUT * W_OUT);

    const int r0 = half * (WARPS * RPW) + warp * RPW;   // strip start row
    const int c0 = lane * 4;                            // input col base
    const int oc = lane * 8;                            // output col base

    float hp[8];                                        // h(n-1), rolled
    if (r0 == 0) {
        #pragma unroll
        for (int j = 0; j < 8; ++j) hp[j] = 0.0f;
    } else {
        float4 a = *reinterpret_cast<const float4*>(xi + (r0 - 1) * W_IN + c0);
        compute_h(a, lane, hp);
    }

    #pragma unroll
    for (int base = r0; base < r0 + RPW; base += CHUNK) {
        float4 v[CHUNK];
        #pragma unroll
        for (int k = 0; k < CHUNK; ++k)
            v[k] = *reinterpret_cast<const float4*>(xi + (base + k) * W_IN + c0);

        #pragma unroll
        for (int k = 0; k < CHUNK; ++k) {
            const int n = base + k;
            float h[8];
            compute_h(v[k], lane, h);

            // out row 2n-1 = 0.75*h(n-1) + 0.25*h(n)   (row -1 doesn't exist)
            if (n > 0)
                store_row_v8(oi + (2 * n - 1) * W_OUT + oc, hp, h, 0.75f, 0.25f);
            // out row 2n   = 0.25*h(n-1) + 0.75*h(n)
            store_row_v8(oi + (2 * n) * W_OUT + oc, hp, h, 0.25f, 0.75f);

            #pragma unroll
            for (int j = 0; j < 8; ++j) hp[j] = h[j];
        }
    }

    // last output row 2H-1 = 0.75*h(H-1), owned by the last strip
    if (r0 + RPW == H_IN) {
        float z[8] = {0, 0, 0, 0, 0, 0, 0, 0};
        store_row_v8(oi + (H_OUT - 1) * W_OUT + oc, hp, z, 0.75f, 0.0f);
    }
}

extern "C" void kernel_launch(void* const* d_in, const int* in_sizes, int n_in,
                              void* d_out, int out_size) {
    const float* x = (const float*)d_in[0];   // [8,128,128,128] fp32
    // d_in[1] is the fixed 4x4 binomial kernel; weights folded into code.
    float* out = (float*)d_out;               // [8,128,256,256] fp32

    const int n_img = in_sizes[0] / (H_IN * W_IN);   // B*C = 1024
    Upsample_63797444215162_kernel<<<n_img * 2, WARPS * 32>>>(x, out);
}